// round 9
// baseline (speedup 1.0000x reference)
#include <cuda_runtime.h>
#include <cuda_bf16.h>
#include <cstdint>

// ===========================================================================
// TransConvLayer reduction (validated R4/R6/R7/R8):
//   out[n,:] = source[n,:] @ Wbar^T + bbar
// Round 9: 512 threads / 16 warps (8 row-groups x 2 col-groups, warp tile
// 16x32) for 4 warps/SMSP latency hiding; regs ~100/thread (was 254).
// Same fused bf16x3 math: D = Xhi*Whi + Xlo*Whi + Xhi*Wlo.
// K-chunked double-buffered staging pipeline retained.
// ===========================================================================

#define IN_CH   256
#define OUT_CH  64
#define TILE_M  128
#define THREADS 512            // 16 warps
#define KCH     64             // K per chunk
#define NCH     4              // chunks

// SMEM layout (bytes from 1024-aligned base):
//   W hi/lo: 64 rows x 512 B (full K), swizzled          -> 64 KB
//   X pipe : 2 stages x (hi,lo) x [128 rows x 128 B]     -> 64 KB
#define OFF_WHI  0
#define OFF_WLO  32768
#define OFF_XB   65536
#define XSTAGE   32768          // per-stage (hi+lo)
#define XHALF    16384          // hi or lo within a stage
#define SMEM_SZ  (65536 + 2 * XSTAGE)   // 131072
#define SMEM_DYN (SMEM_SZ + 1024)

// ---- device weight globals --------------------------------------------------
__device__ __nv_bfloat16 g_Whi[OUT_CH * IN_CH];   // [d][k] row-major
__device__ __nv_bfloat16 g_Wlo[OUT_CH * IN_CH];
__device__ float         g_b[OUT_CH];

__global__ void prep_kernel(const float* __restrict__ Wv_w,
                            const float* __restrict__ Wv_b) {
    int idx = blockIdx.x * blockDim.x + threadIdx.x;   // 0..16383
    if (idx < OUT_CH * IN_CH) {
        int d = idx >> 8;
        int k = idx & 255;
        float s = 0.f;
        #pragma unroll
        for (int h = 0; h < 4; ++h) s += Wv_w[(h * OUT_CH + d) * IN_CH + k];
        float w = 0.25f * s;
        __nv_bfloat16 hi = __float2bfloat16(w);
        g_Whi[idx] = hi;
        g_Wlo[idx] = __float2bfloat16(w - __bfloat162float(hi));
    }
    if (idx < OUT_CH) {
        float s = 0.f;
        #pragma unroll
        for (int h = 0; h < 4; ++h) s += Wv_b[h * OUT_CH + idx];
        g_b[idx] = 0.25f * s;
    }
}

// ---- helpers ----------------------------------------------------------------

__device__ __forceinline__ uint32_t smem_u32(const void* p) {
    uint32_t a;
    asm("{ .reg .u64 t; cvta.to.shared.u64 t, %1; cvt.u32.u64 %0, t; }"
        : "=r"(a) : "l"(p));
    return a;
}

__device__ __forceinline__ void ldsm_x4(uint32_t& r0, uint32_t& r1,
                                        uint32_t& r2, uint32_t& r3,
                                        uint32_t addr) {
    asm volatile("ldmatrix.sync.aligned.m8n8.x4.shared.b16 {%0,%1,%2,%3}, [%4];"
                 : "=r"(r0), "=r"(r1), "=r"(r2), "=r"(r3) : "r"(addr));
}

__device__ __forceinline__ void mma_16816(float* c, const uint32_t* a,
                                          const uint32_t* b) {
    asm volatile(
        "mma.sync.aligned.m16n8k16.row.col.f32.bf16.bf16.f32 "
        "{%0,%1,%2,%3}, {%4,%5,%6,%7}, {%8,%9}, {%0,%1,%2,%3};"
        : "+f"(c[0]), "+f"(c[1]), "+f"(c[2]), "+f"(c[3])
        : "r"(a[0]), "r"(a[1]), "r"(a[2]), "r"(a[3]), "r"(b[0]), "r"(b[1]));
}

// split a float pair into packed bf16x2 hi / lo words
__device__ __forceinline__ void split_pair(float x, float y,
                                           uint32_t& h, uint32_t& l) {
    __nv_bfloat162 hh = __floats2bfloat162_rn(x, y);
    float2 hf = __bfloat1622float2(hh);
    __nv_bfloat162 ll = __floats2bfloat162_rn(x - hf.x, y - hf.y);
    h = *reinterpret_cast<const uint32_t*>(&hh);
    l = *reinterpret_cast<const uint32_t*>(&ll);
}

// ---- main kernel --------------------------------------------------------------

__global__ __launch_bounds__(THREADS, 1)
void gemm_kernel(const float* __restrict__ X, float* __restrict__ Y, int N) {
    extern __shared__ char smem_raw[];
    uint32_t raw  = smem_u32(smem_raw);
    uint32_t base = (raw + 1023) & ~1023u;
    char*    sm   = smem_raw + (base - raw);

    const int tid  = threadIdx.x;
    const int wid  = tid >> 5;
    const int lid  = tid & 31;
    const int wr   = wid >> 1;            // 0..7  -> rows wr*16
    const int wc   = wid & 1;             // 0..1  -> cols wc*32
    const int row0 = blockIdx.x * TILE_M;

    // ---- stage W hi/lo once (full K): 64 rows x 32 chunks, swizzled ----
    #pragma unroll
    for (int it = 0; it < 4; ++it) {
        int idx = it * THREADS + tid;     // 0..2047
        int r   = idx >> 5;
        int c   = idx & 31;
        uint32_t off = (uint32_t)(r * 512 + ((c ^ (r & 7)) << 4));
        *reinterpret_cast<uint4*>(sm + OFF_WHI + off) =
            *reinterpret_cast<const uint4*>(g_Whi + r * IN_CH + c * 8);
        *reinterpret_cast<uint4*>(sm + OFF_WLO + off) =
            *reinterpret_cast<const uint4*>(g_Wlo + r * IN_CH + c * 8);
    }

    // ---- chunk staging helpers ----
    // chunk = 128 rows x 64 k fp32 -> bf16 hi/lo [128 rows x 128 B], swz c^r&7
    auto load_chunk = [&](float4* pend, int kc) {
        const int kc0 = kc * KCH;
        #pragma unroll
        for (int it = 0; it < 2; ++it) {
            int idx = it * THREADS + tid;   // 0..1023
            int r   = idx >> 3;
            int c   = idx & 7;
            int gr  = row0 + r;
            if (gr >= N) gr = N - 1;
            const float4* gp = reinterpret_cast<const float4*>(
                X + (size_t)gr * IN_CH + kc0 + c * 8);
            pend[2 * it]     = gp[0];
            pend[2 * it + 1] = gp[1];
        }
    };
    auto cvt_sts_chunk = [&](const float4* pend, int st) {
        char* dhi = sm + OFF_XB + st * XSTAGE;
        char* dlo = dhi + XHALF;
        #pragma unroll
        for (int it = 0; it < 2; ++it) {
            int idx = it * THREADS + tid;
            int r   = idx >> 3;
            int c   = idx & 7;
            float4 a = pend[2 * it];
            float4 b = pend[2 * it + 1];
            uint4 h, l;
            split_pair(a.x, a.y, h.x, l.x);
            split_pair(a.z, a.w, h.y, l.y);
            split_pair(b.x, b.y, h.z, l.z);
            split_pair(b.z, b.w, h.w, l.w);
            uint32_t off = (uint32_t)(r * 128 + ((c ^ (r & 7)) << 4));
            *reinterpret_cast<uint4*>(dhi + off) = h;
            *reinterpret_cast<uint4*>(dlo + off) = l;
        }
    };

    // ---- prologue: stage chunk 0 ----
    {
        float4 pend[4];
        load_chunk(pend, 0);
        cvt_sts_chunk(pend, 0);
    }
    __syncthreads();

    // ---- per-lane ldmatrix address components ----
    // A: warp tile 16 rows, chunk layout (row stride 128 B, chunks 0..7)
    const int rA    = wr * 16 + ((lid >> 3) & 1) * 8 + (lid & 7);
    const int chA   = lid >> 4;
    const int swzA  = rA & 7;
    const uint32_t aRow = (uint32_t)(rA * 128);
    // B: full-K layout (row stride 512 B, chunks 0..31), 32 cols via 2 x4 loads
    const int rBb   = wc * 32 + ((lid >> 4) & 1) * 8 + (lid & 7);
    const int chB   = (lid >> 3) & 1;
    const int swzB  = rBb & 7;
    const uint32_t bRow0 = (uint32_t)(rBb * 512);
    const uint32_t bRow1 = (uint32_t)((rBb + 16) * 512);

    float acc[4][4];
    #pragma unroll
    for (int nt = 0; nt < 4; ++nt)
        #pragma unroll
        for (int q = 0; q < 4; ++q) acc[nt][q] = 0.f;

    const uint32_t whi = base + OFF_WHI;
    const uint32_t wlo = base + OFF_WLO;

    // ---- pipelined chunk loop ----
    #pragma unroll
    for (int kc = 0; kc < NCH; ++kc) {
        // issue next chunk's global loads BEFORE this chunk's MMA
        float4 pend[4];
        if (kc < NCH - 1) load_chunk(pend, kc + 1);

        const uint32_t xhi = base + OFF_XB + (uint32_t)(kc & 1) * XSTAGE;
        const uint32_t xlo = xhi + XHALF;

        #pragma unroll
        for (int ks = 0; ks < 4; ++ks) {
            const int ksg = kc * 4 + ks;
            const uint32_t oA = (uint32_t)(((2 * ks  + chA) ^ swzA) << 4);
            const uint32_t oB = (uint32_t)(((2 * ksg + chB) ^ swzB) << 4);

            uint32_t ah[4], bh[8];
            ldsm_x4(ah[0], ah[1], ah[2], ah[3], xhi + aRow + oA);
            ldsm_x4(bh[0], bh[1], bh[2], bh[3], whi + bRow0 + oB);
            ldsm_x4(bh[4], bh[5], bh[6], bh[7], whi + bRow1 + oB);

            // main term: Xhi * Whi
            #pragma unroll
            for (int nt = 0; nt < 4; ++nt)
                mma_16816(acc[nt], ah, bh + 2 * nt);

            // correction 1: Xlo * Whi (reuse bh)
            {
                uint32_t al[4];
                ldsm_x4(al[0], al[1], al[2], al[3], xlo + aRow + oA);
                #pragma unroll
                for (int nt = 0; nt < 4; ++nt)
                    mma_16816(acc[nt], al, bh + 2 * nt);
            }
            // correction 2: Xhi * Wlo (reuse ah)
            {
                uint32_t bl[8];
                ldsm_x4(bl[0], bl[1], bl[2], bl[3], wlo + bRow0 + oB);
                ldsm_x4(bl[4], bl[5], bl[6], bl[7], wlo + bRow1 + oB);
                #pragma unroll
                for (int nt = 0; nt < 4; ++nt)
                    mma_16816(acc[nt], ah, bl + 2 * nt);
            }
        }

        // convert + store next chunk into the other stage, then sync
        if (kc < NCH - 1) cvt_sts_chunk(pend, (kc + 1) & 1);
        __syncthreads();
    }

    // ---- epilogue: D frag -> global, + bias ----
    const int qr = lid >> 2;               // 0..7
    const int qc = (lid & 3) * 2;
    int r_lo = row0 + wr * 16 + qr;
    #pragma unroll
    for (int nt = 0; nt < 4; ++nt) {
        int col = wc * 32 + nt * 8 + qc;
        float b0 = g_b[col], b1 = g_b[col + 1];
        if (r_lo < N) {
            float2 v = make_float2(acc[nt][0] + b0, acc[nt][1] + b1);
            *reinterpret_cast<float2*>(Y + (size_t)r_lo * OUT_CH + col) = v;
        }
        if (r_lo + 8 < N) {
            float2 v = make_float2(acc[nt][2] + b0, acc[nt][3] + b1);
            *reinterpret_cast<float2*>(Y + (size_t)(r_lo + 8) * OUT_CH + col) = v;
        }
    }
}

// ---------------------------------------------------------------------------

extern "C" void kernel_launch(void* const* d_in, const int* in_sizes, int n_in,
                              void* d_out, int out_size) {
    // inputs: query_input, source_input, Wq_w, Wq_b, Wk_w, Wk_b, Wv_w, Wv_b
    const float* src  = (const float*)d_in[1];
    const float* Wv_w = (const float*)d_in[6];
    const float* Wv_b = (const float*)d_in[7];
    float* out = (float*)d_out;
    const int N = in_sizes[1] / IN_CH;

    cudaFuncSetAttribute(gemm_kernel,
                         cudaFuncAttributeMaxDynamicSharedMemorySize, SMEM_DYN);

    prep_kernel<<<64, 256>>>(Wv_w, Wv_b);
    const int grid = (N + TILE_M - 1) / TILE_M;
    gemm_kernel<<<grid, THREADS, SMEM_DYN>>>(src, out, N);
}

// round 10
// speedup vs baseline: 1.0961x; 1.0961x over previous
#include <cuda_runtime.h>
#include <cuda_bf16.h>
#include <cstdint>

// ===========================================================================
// TransConvLayer reduction (validated R4/R6-R9):
//   out[n,:] = source[n,:] @ Wbar^T + bbar
// Round 10: 2 CTAs/SM for inter-CTA phase overlap.
//   - 8 warps, warp tile 32x32 (col-groups=2, row-groups=4: minimum LDSM
//     replication = 512 KB/CTA).
//   - smem 96 KB (K chunked in 2 halves of 128; X 64 KB + W 32 KB reused)
//     -> 2 CTAs resident; staging of one CTA hides under MMA of the other.
//   - __launch_bounds__(256,2) caps regs at 128 (no reg-staged pipeline).
// Math identical: D = Xhi*Whi + Xlo*Whi + Xhi*Wlo (fused bf16x3).
// ===========================================================================

#define IN_CH   256
#define OUT_CH  64
#define TILE_M  128
#define THREADS 256            // 8 warps: 4 row-groups x 2 col-groups
#define KCH     128            // K per chunk
#define NCH     2              // chunks

// SMEM layout (bytes from 1024-aligned base). Row stride 256 B (128 bf16).
#define OFF_WHI  0             // W chunk hi: 64 x 256 B = 16 KB
#define OFF_WLO  16384         // W chunk lo: 16 KB
#define OFF_XHI  32768         // X chunk hi: 128 x 256 B = 32 KB
#define OFF_XLO  65536         // X chunk lo: 32 KB
#define SMEM_SZ  98304         // 96 KB
#define SMEM_DYN (SMEM_SZ + 1024)

// ---- device weight globals --------------------------------------------------
__device__ __nv_bfloat16 g_Whi[OUT_CH * IN_CH];   // [d][k] row-major
__device__ __nv_bfloat16 g_Wlo[OUT_CH * IN_CH];
__device__ float         g_b[OUT_CH];

__global__ void prep_kernel(const float* __restrict__ Wv_w,
                            const float* __restrict__ Wv_b) {
    int idx = blockIdx.x * blockDim.x + threadIdx.x;   // 0..16383
    if (idx < OUT_CH * IN_CH) {
        int d = idx >> 8;
        int k = idx & 255;
        float s = 0.f;
        #pragma unroll
        for (int h = 0; h < 4; ++h) s += Wv_w[(h * OUT_CH + d) * IN_CH + k];
        float w = 0.25f * s;
        __nv_bfloat16 hi = __float2bfloat16(w);
        g_Whi[idx] = hi;
        g_Wlo[idx] = __float2bfloat16(w - __bfloat162float(hi));
    }
    if (idx < OUT_CH) {
        float s = 0.f;
        #pragma unroll
        for (int h = 0; h < 4; ++h) s += Wv_b[h * OUT_CH + idx];
        g_b[idx] = 0.25f * s;
    }
}

// ---- helpers ----------------------------------------------------------------

__device__ __forceinline__ uint32_t smem_u32(const void* p) {
    uint32_t a;
    asm("{ .reg .u64 t; cvta.to.shared.u64 t, %1; cvt.u32.u64 %0, t; }"
        : "=r"(a) : "l"(p));
    return a;
}

__device__ __forceinline__ void ldsm_x4(uint32_t& r0, uint32_t& r1,
                                        uint32_t& r2, uint32_t& r3,
                                        uint32_t addr) {
    asm volatile("ldmatrix.sync.aligned.m8n8.x4.shared.b16 {%0,%1,%2,%3}, [%4];"
                 : "=r"(r0), "=r"(r1), "=r"(r2), "=r"(r3) : "r"(addr));
}

__device__ __forceinline__ void mma_16816(float* c, const uint32_t* a,
                                          const uint32_t* b) {
    asm volatile(
        "mma.sync.aligned.m16n8k16.row.col.f32.bf16.bf16.f32 "
        "{%0,%1,%2,%3}, {%4,%5,%6,%7}, {%8,%9}, {%0,%1,%2,%3};"
        : "+f"(c[0]), "+f"(c[1]), "+f"(c[2]), "+f"(c[3])
        : "r"(a[0]), "r"(a[1]), "r"(a[2]), "r"(a[3]), "r"(b[0]), "r"(b[1]));
}

// split a float pair into packed bf16x2 hi / lo words
__device__ __forceinline__ void split_pair(float x, float y,
                                           uint32_t& h, uint32_t& l) {
    __nv_bfloat162 hh = __floats2bfloat162_rn(x, y);
    float2 hf = __bfloat1622float2(hh);
    __nv_bfloat162 ll = __floats2bfloat162_rn(x - hf.x, y - hf.y);
    h = *reinterpret_cast<const uint32_t*>(&hh);
    l = *reinterpret_cast<const uint32_t*>(&ll);
}

// ---- main kernel --------------------------------------------------------------

__global__ __launch_bounds__(THREADS, 2)
void gemm_kernel(const float* __restrict__ X, float* __restrict__ Y, int N) {
    extern __shared__ char smem_raw[];
    uint32_t raw  = smem_u32(smem_raw);
    uint32_t base = (raw + 1023) & ~1023u;
    char*    sm   = smem_raw + (base - raw);

    const int tid  = threadIdx.x;
    const int wid  = tid >> 5;
    const int lid  = tid & 31;
    const int wr   = wid >> 1;            // 0..3  -> rows wr*32
    const int wc   = wid & 1;             // 0..1  -> cols wc*32
    const int row0 = blockIdx.x * TILE_M;

    // ---- per-lane ldmatrix address components (row stride 256 B) ----
    // A: (row+0,k0),(row+8,k0),(row+0,k8),(row+8,k8)
    const int rA    = wr * 32 + ((lid >> 3) & 1) * 8 + (lid & 7);
    const int chA   = lid >> 4;
    const int swzA  = rA & 7;
    const uint32_t aRow0 = (uint32_t)(rA * 256);
    const uint32_t aRow1 = (uint32_t)((rA + 16) * 256);
    // B: (n+0,k0),(n+0,k8),(n+8,k0),(n+8,k8)
    const int rBb   = wc * 32 + ((lid >> 4) & 1) * 8 + (lid & 7);
    const int chB   = (lid >> 3) & 1;
    const int swzB  = rBb & 7;
    const uint32_t bRow0 = (uint32_t)(rBb * 256);
    const uint32_t bRow1 = (uint32_t)((rBb + 16) * 256);

    const uint32_t whi = base + OFF_WHI;
    const uint32_t wlo = base + OFF_WLO;
    const uint32_t xhi = base + OFF_XHI;
    const uint32_t xlo = base + OFF_XLO;

    float acc[2][4][4];
    #pragma unroll
    for (int mt = 0; mt < 2; ++mt)
        #pragma unroll
        for (int nt = 0; nt < 4; ++nt)
            #pragma unroll
            for (int q = 0; q < 4; ++q) acc[mt][nt][q] = 0.f;

    #pragma unroll 1
    for (int kc = 0; kc < NCH; ++kc) {
        const int kc0 = kc * KCH;

        // ---- stage W chunk hi/lo: 64 rows x 16 chunks of 16B, swizzled ----
        #pragma unroll
        for (int it = 0; it < 4; ++it) {
            int idx = it * THREADS + tid;     // 0..1023
            int r   = idx >> 4;
            int c   = idx & 15;
            uint32_t off = (uint32_t)(r * 256 + ((c ^ (r & 7)) << 4));
            *reinterpret_cast<uint4*>(sm + OFF_WHI + off) =
                *reinterpret_cast<const uint4*>(g_Whi + r * IN_CH + kc0 + c * 8);
            *reinterpret_cast<uint4*>(sm + OFF_WLO + off) =
                *reinterpret_cast<const uint4*>(g_Wlo + r * IN_CH + kc0 + c * 8);
        }

        // ---- stage X chunk: fp32 -> bf16 hi/lo, swizzled STS ----
        #pragma unroll
        for (int it = 0; it < 8; ++it) {
            int idx = it * THREADS + tid;     // 0..2047
            int r   = idx >> 4;               // 0..127
            int c   = idx & 15;               // 16B bf16 chunk = 8 k values
            int gr  = row0 + r;
            if (gr >= N) gr = N - 1;          // clamp; epilogue guards rows
            const float4* gp = reinterpret_cast<const float4*>(
                X + (size_t)gr * IN_CH + kc0 + c * 8);
            float4 a = gp[0];
            float4 b = gp[1];
            uint4 h, l;
            split_pair(a.x, a.y, h.x, l.x);
            split_pair(a.z, a.w, h.y, l.y);
            split_pair(b.x, b.y, h.z, l.z);
            split_pair(b.z, b.w, h.w, l.w);
            uint32_t off = (uint32_t)(r * 256 + ((c ^ (r & 7)) << 4));
            *reinterpret_cast<uint4*>(sm + OFF_XHI + off) = h;
            *reinterpret_cast<uint4*>(sm + OFF_XLO + off) = l;
        }
        __syncthreads();

        // ---- fused 3-term MMA over this chunk: 8 k-steps ----
        #pragma unroll
        for (int ks = 0; ks < 8; ++ks) {
            const uint32_t oA = (uint32_t)(((2 * ks + chA) ^ swzA) << 4);
            const uint32_t oB = (uint32_t)(((2 * ks + chB) ^ swzB) << 4);

            uint32_t ah0[4], ah1[4], bh[8];
            ldsm_x4(ah0[0], ah0[1], ah0[2], ah0[3], xhi + aRow0 + oA);
            ldsm_x4(ah1[0], ah1[1], ah1[2], ah1[3], xhi + aRow1 + oA);
            ldsm_x4(bh[0], bh[1], bh[2], bh[3], whi + bRow0 + oB);
            ldsm_x4(bh[4], bh[5], bh[6], bh[7], whi + bRow1 + oB);

            // main term: Xhi * Whi
            #pragma unroll
            for (int nt = 0; nt < 4; ++nt) {
                mma_16816(acc[0][nt], ah0, bh + 2 * nt);
                mma_16816(acc[1][nt], ah1, bh + 2 * nt);
            }
            // correction 1: Xlo * Whi (reuse bh)
            {
                uint32_t al0[4], al1[4];
                ldsm_x4(al0[0], al0[1], al0[2], al0[3], xlo + aRow0 + oA);
                ldsm_x4(al1[0], al1[1], al1[2], al1[3], xlo + aRow1 + oA);
                #pragma unroll
                for (int nt = 0; nt < 4; ++nt) {
                    mma_16816(acc[0][nt], al0, bh + 2 * nt);
                    mma_16816(acc[1][nt], al1, bh + 2 * nt);
                }
            }
            // correction 2: Xhi * Wlo (reuse ah0/ah1)
            {
                uint32_t bl[8];
                ldsm_x4(bl[0], bl[1], bl[2], bl[3], wlo + bRow0 + oB);
                ldsm_x4(bl[4], bl[5], bl[6], bl[7], wlo + bRow1 + oB);
                #pragma unroll
                for (int nt = 0; nt < 4; ++nt) {
                    mma_16816(acc[0][nt], ah0, bl + 2 * nt);
                    mma_16816(acc[1][nt], ah1, bl + 2 * nt);
                }
            }
        }
        __syncthreads();   // before buffers are overwritten by next chunk
    }

    // ---- epilogue: D frag -> global, + bias ----
    const int qr = lid >> 2;               // 0..7
    const int qc = (lid & 3) * 2;
    #pragma unroll
    for (int mt = 0; mt < 2; ++mt) {
        int r_lo = row0 + wr * 32 + mt * 16 + qr;
        #pragma unroll
        for (int nt = 0; nt < 4; ++nt) {
            int col = wc * 32 + nt * 8 + qc;
            float b0 = g_b[col], b1 = g_b[col + 1];
            if (r_lo < N) {
                float2 v = make_float2(acc[mt][nt][0] + b0,
                                       acc[mt][nt][1] + b1);
                *reinterpret_cast<float2*>(Y + (size_t)r_lo * OUT_CH + col) = v;
            }
            if (r_lo + 8 < N) {
                float2 v = make_float2(acc[mt][nt][2] + b0,
                                       acc[mt][nt][3] + b1);
                *reinterpret_cast<float2*>(Y + (size_t)(r_lo + 8) * OUT_CH + col) = v;
            }
        }
    }
}

// ---------------------------------------------------------------------------

extern "C" void kernel_launch(void* const* d_in, const int* in_sizes, int n_in,
                              void* d_out, int out_size) {
    // inputs: query_input, source_input, Wq_w, Wq_b, Wk_w, Wk_b, Wv_w, Wv_b
    const float* src  = (const float*)d_in[1];
    const float* Wv_w = (const float*)d_in[6];
    const float* Wv_b = (const float*)d_in[7];
    float* out = (float*)d_out;
    const int N = in_sizes[1] / IN_CH;

    cudaFuncSetAttribute(gemm_kernel,
                         cudaFuncAttributeMaxDynamicSharedMemorySize, SMEM_DYN);

    prep_kernel<<<64, 256>>>(Wv_w, Wv_b);
    const int grid = (N + TILE_M - 1) / TILE_M;
    gemm_kernel<<<grid, THREADS, SMEM_DYN>>>(src, out, N);
}